// round 13
// baseline (speedup 1.0000x reference)
#include <cuda_runtime.h>

// MetaSR collapsed to a sub-pixel 3x3 conv (see R2 analysis):
//   rel = (j&1)*0.5 exactly, r_rev = 0.5 exactly -> MLP input has 4 values
//   (one per 2x2 phase) -> pw collapses to 4 tables of (576,3).
// pred[b,(2y+dy)*128+2x+dx,o] = sum_{c,ky,kx} feat[b,c,y+ky-1,x+kx-1]
//                                  * pw[dy*2+dx][(c*9+ky*3+kx)*3+o]
//
// R10: k_main = 32-thread blocks (1 warp = 8 cg x 4 quads), weights via
// __ldg from L1 (no smem). 8 FFMA2 per L1 wavefront; 1024 blocks, even wave.

#define NB 4
#define NQ 16384
#define NOUT 1728
#define PH 66   // padded H/W

// pw layout: idx = ((cc*9 + tap)*8 + cg)*12 + pat*3 + o   (c = cg*8+cc)
// Octet LDS/LDG.128 stride = 12 floats: cg*12 mod 32 covers all 32 banks
// exactly once -> 1 wavefront per 128-bit weight load (4-way sub broadcast).
__device__ __align__(16) float g_pw[576 * 12];                  // 27648 B
__device__ __align__(16) float g_featP[NB * PH * PH * 64];      // padded, ch-last

// ---------------------------------------------------------------------------
// f32x2 packed helpers (PTX-only path; ptxas won't auto-fuse)
// ---------------------------------------------------------------------------
__device__ __forceinline__ unsigned long long pk2(float a, float b) {
    unsigned long long r;
    asm("mov.b64 %0, {%1, %2};" : "=l"(r) : "f"(a), "f"(b));
    return r;
}
__device__ __forceinline__ void upk2(unsigned long long v, float& a, float& b) {
    asm("mov.b64 {%0, %1}, %2;" : "=f"(a), "=f"(b) : "l"(v));
}
__device__ __forceinline__ void ffma2(unsigned long long& d,
                                      unsigned long long a, unsigned long long b) {
    asm("fma.rn.f32x2 %0, %1, %2, %0;" : "+l"(d) : "l"(a), "l"(b));
}

// ---------------------------------------------------------------------------
// Prep kernel: 547 blocks x 256 threads, role-split (unchanged from R7 except
// the pw output indexing, which now targets the cg8 layout).
// ---------------------------------------------------------------------------
__global__ __launch_bounds__(256) void k_prep(const float* __restrict__ feat,
                                              const float* __restrict__ w1,
                                              const float* __restrict__ b1,
                                              const float* __restrict__ w2,
                                              const float* __restrict__ b2) {
    __shared__ float sm[2080];
    int bi = blockIdx.x;
    int t = threadIdx.x;

    if (bi < 512) {
        // ---- transpose: block = (b, y, c-half). tile[32][65] in sm.
        float(*tile)[65] = reinterpret_cast<float(*)[65]>(sm);
        int b = bi >> 7;
        int y = (bi >> 1) & 63;
        int ch = (bi & 1) * 32;
        int xi = t & 63;
        int ci = t >> 6;           // 0..3
#pragma unroll
        for (int pass = 0; pass < 8; ++pass) {
            int cl = pass * 4 + ci;
            tile[cl][xi] = feat[((b * 64 + ch + cl) * 64 + y) * 64 + xi];
        }
        __syncthreads();
        int cl = t & 31;
        int xj = t >> 5;           // 0..7
#pragma unroll
        for (int pass = 0; pass < 8; ++pass) {
            int x = pass * 8 + xj;
            g_featP[((b * PH + y + 1) * PH + x + 1) * 64 + ch + cl] = tile[cl][x];
        }
    } else if (bi < 539) {
        // ---- pw tables
        float* hdd = sm;            // [4][256]
        float* part = sm + 1024;    // [4][4][64]
        {
            float a0 = w1[t];
            float a1 = w1[256 + t];
            float a2 = w1[512 + t];
            float bb = b1[t];
#pragma unroll
            for (int pat = 0; pat < 4; ++pat) {
                float ry = (pat >> 1) ? 0.5f : 0.0f;
                float rx = (pat & 1) ? 0.5f : 0.0f;
                float v = ry * a0 + rx * a1 + 0.5f * a2 + bb;
                hdd[pat * 256 + t] = v > 0.0f ? v : 0.0f;
            }
        }
        __syncthreads();
        int jt = t & 63;
        int hc = t >> 6;
        int j = (bi - 512) * 64 + jt;
        int hb = hc * 64;
        float a0 = 0.f, a1 = 0.f, a2 = 0.f, a3 = 0.f;
        const float* w2p = w2 + hb * NOUT + j;
#pragma unroll 8
        for (int hh = 0; hh < 64; ++hh) {
            float wv = w2p[hh * NOUT];
            a0 += hdd[0 * 256 + hb + hh] * wv;
            a1 += hdd[1 * 256 + hb + hh] * wv;
            a2 += hdd[2 * 256 + hb + hh] * wv;
            a3 += hdd[3 * 256 + hb + hh] * wv;
        }
        part[(hc * 4 + 0) * 64 + jt] = a0;
        part[(hc * 4 + 1) * 64 + jt] = a1;
        part[(hc * 4 + 2) * 64 + jt] = a2;
        part[(hc * 4 + 3) * 64 + jt] = a3;
        __syncthreads();
        if (hc == 0) {
            float bias = b2[j];
            int k = j / 3;
            int o = j - k * 3;
            int c = k / 9;
            int tap = k - c * 9;
            int cgi = c >> 3;          // cg8 layout
            int cci = c & 7;
            int base = ((cci * 9 + tap) * 8 + cgi) * 12 + o;
#pragma unroll
            for (int pat = 0; pat < 4; ++pat) {
                float s = part[(0 * 4 + pat) * 64 + jt] + part[(1 * 4 + pat) * 64 + jt] +
                          part[(2 * 4 + pat) * 64 + jt] + part[(3 * 4 + pat) * 64 + jt] + bias;
                g_pw[base + pat * 3] = s;
            }
        }
    } else {
        // ---- halo zero
        int hb = bi - 539;
        int b = hb >> 1;
        int halfsel = hb & 1;
        for (int idx = t; idx < 130 * 64; idx += 256) {
            int p = halfsel * 130 + (idx >> 6);
            int c = idx & 63;
            int y, x;
            if (p < 66) { y = 0; x = p; }
            else if (p < 132) { y = 65; x = p - 66; }
            else if (p < 196) { x = 0; y = p - 131; }
            else { x = 65; y = p - 195; }
            g_featP[((b * PH + y) * PH + x) * 64 + c] = 0.0f;
        }
    }
}

// ---------------------------------------------------------------------------
// Main conv kernel: 1024 blocks x 32 threads (1 warp), ~7 blocks/SM.
// Warp = 4 quads (4 x-adjacent LR px each); lane = sub*8 + cg:
//   cg (0..7) owns 8 channels, sub (0..3) selects the quad.
// Thread: 8 ch x 9 taps x 4 px x 12 out = 1728 packed f32x2 FMAs.
// Weights via __ldg (L1); 3-stage reduce-scatter over cg; 3x float2 STG.
// ---------------------------------------------------------------------------
__global__ __launch_bounds__(32) void k_main(float* __restrict__ out) {
    int lane = threadIdx.x;
    int cg = lane & 7;
    int sub = lane >> 3;
    int quad = blockIdx.x * 4 + sub;      // 0..4095 (4 per block share b,y)
    int b = quad >> 10;
    int rem = quad & 1023;
    int y = rem >> 4;
    int x0 = (rem & 15) << 2;             // LR x of first pixel (padded col x0..x0+5)

    unsigned long long acc[4][6];
#pragma unroll
    for (int px = 0; px < 4; ++px)
#pragma unroll
        for (int p = 0; p < 6; ++p) acc[px][p] = 0ull;

#pragma unroll
    for (int ky = 0; ky < 3; ++ky) {
        const float* rp = g_featP + ((b * PH + y + ky) * PH + x0) * 64 + cg * 8;
        float fr[6][8];
#pragma unroll
        for (int i = 0; i < 6; ++i) {
            float4 v0 = __ldg(reinterpret_cast<const float4*>(rp + i * 64));
            float4 v1 = __ldg(reinterpret_cast<const float4*>(rp + i * 64 + 4));
            fr[i][0] = v0.x; fr[i][1] = v0.y; fr[i][2] = v0.z; fr[i][3] = v0.w;
            fr[i][4] = v1.x; fr[i][5] = v1.y; fr[i][6] = v1.z; fr[i][7] = v1.w;
        }
#pragma unroll
        for (int kx = 0; kx < 3; ++kx) {
#pragma unroll
            for (int cc = 0; cc < 8; ++cc) {
                const ulonglong2* wp = reinterpret_cast<const ulonglong2*>(
                    g_pw + ((cc * 9 + ky * 3 + kx) * 8 + cg) * 12);
                ulonglong2 w01 = __ldg(wp);
                ulonglong2 w23 = __ldg(wp + 1);
                ulonglong2 w45 = __ldg(wp + 2);
#pragma unroll
                for (int px = 0; px < 4; ++px) {
                    float fv = fr[kx + px][cc];
                    unsigned long long fv2 = pk2(fv, fv);
                    ffma2(acc[px][0], fv2, w01.x);
                    ffma2(acc[px][1], fv2, w01.y);
                    ffma2(acc[px][2], fv2, w23.x);
                    ffma2(acc[px][3], fv2, w23.y);
                    ffma2(acc[px][4], fv2, w45.x);
                    ffma2(acc[px][5], fv2, w45.y);
                }
            }
        }
    }

    // Unpack to 48 scalars: v[j], j = px*12 + pat*3 + o (pat = dy*2+dx)
    float v[48];
#pragma unroll
    for (int px = 0; px < 4; ++px)
#pragma unroll
        for (int p = 0; p < 6; ++p) {
            float a, bb;
            upk2(acc[px][p], a, bb);
            v[px * 12 + 2 * p] = a;
            v[px * 12 + 2 * p + 1] = bb;
        }

    // Reduce-scatter over cg bits {1,2,4}: 48 -> 24 -> 12 -> 6 values.
#pragma unroll
    for (int m = 1, n = 48; m < 8; m <<= 1, n >>= 1) {
        int half = n >> 1;
        bool hi = (cg & m) != 0;
#pragma unroll
        for (int i = 0; i < 48; ++i) {
            if (i >= half) break;
            float send = hi ? v[i] : v[i + half];
            float r = __shfl_xor_sync(0xffffffffu, send, m);
            v[i] = (hi ? v[i + half] : v[i]) + r;
        }
    }

    // Lane owns j = base..base+5: base = 24*b0 + 12*b1 + 6*b2 (bits of cg).
    // (px, dy) fixed; the 6 values are (dx, o)-contiguous in output memory.
    int base = 24 * (cg & 1) + 12 * ((cg >> 1) & 1) + 6 * ((cg >> 2) & 1);
    int px = base / 12;
    int r12 = base - px * 12;
    int dy = r12 >= 6;

    int hrq = (2 * y + dy) * 128 + 2 * (x0 + px);
    float2* op = reinterpret_cast<float2*>(out + (b * NQ + hrq) * 3);
    op[0] = make_float2(v[0], v[1]);
    op[1] = make_float2(v[2], v[3]);
    op[2] = make_float2(v[4], v[5]);
}

// ---------------------------------------------------------------------------
// Inputs (metadata order): feat, coord, cell, w1, b1, w2, b2.
// coord/cell are fully determined grids (collapsed analytically).
// ---------------------------------------------------------------------------
extern "C" void kernel_launch(void* const* d_in, const int* in_sizes, int n_in,
                              void* d_out, int out_size) {
    const float* feat = (const float*)d_in[0];
    const float* w1   = (const float*)d_in[3];
    const float* b1   = (const float*)d_in[4];
    const float* w2   = (const float*)d_in[5];
    const float* b2   = (const float*)d_in[6];
    float* out = (float*)d_out;

    k_prep<<<547, 256>>>(feat, w1, b1, w2, b2);
    k_main<<<1024, 32>>>(out);
}

// round 14
// speedup vs baseline: 1.7273x; 1.7273x over previous
#include <cuda_runtime.h>

// MetaSR collapsed to a sub-pixel 3x3 conv (see R2 analysis):
//   rel = (j&1)*0.5 exactly, r_rev = 0.5 exactly -> MLP input has 4 values
//   (one per 2x2 phase) -> pw collapses to 4 tables of (576,3).
// pred[b,(2y+dy)*128+2x+dx,o] = sum_{c,ky,kx} feat[b,c,y+ky-1,x+kx-1]
//                                  * pw[dy*2+dx][(c*9+ky*3+kx)*3+o]
//
// R13: R7 shape (cg16 x 2 subs x px4, smem weights) + explicit software
// pipelining: weight-triple double buffer + fr row double buffer, so LDS and
// LDG latencies hide under the FFMA2 bursts (R7/R8 both ran at exactly 2x
// their pipe floor on dependency stalls).

#define NB 4
#define NQ 16384
#define NOUT 1728
#define PH 66   // padded H/W

// pw layout: idx = ((cc*9 + tap)*16 + cg)*12 + pat*3 + o   (c = cg*4+cc)
__device__ __align__(16) float g_pw[576 * 12];                  // 27648 B
__device__ __align__(16) float g_featP[NB * PH * PH * 64];      // padded, ch-last

// ---------------------------------------------------------------------------
// f32x2 packed helpers (PTX-only path; ptxas won't auto-fuse)
// ---------------------------------------------------------------------------
__device__ __forceinline__ unsigned long long pk2(float a, float b) {
    unsigned long long r;
    asm("mov.b64 %0, {%1, %2};" : "=l"(r) : "f"(a), "f"(b));
    return r;
}
__device__ __forceinline__ void upk2(unsigned long long v, float& a, float& b) {
    asm("mov.b64 {%0, %1}, %2;" : "=f"(a), "=f"(b) : "l"(v));
}
__device__ __forceinline__ void ffma2(unsigned long long& d,
                                      unsigned long long a, unsigned long long b) {
    asm("fma.rn.f32x2 %0, %1, %2, %0;" : "+l"(d) : "l"(a), "l"(b));
}

// ---------------------------------------------------------------------------
// Prep kernel: 547 blocks x 256 threads, role-split (R7 version, cg16 layout).
// ---------------------------------------------------------------------------
__global__ __launch_bounds__(256) void k_prep(const float* __restrict__ feat,
                                              const float* __restrict__ w1,
                                              const float* __restrict__ b1,
                                              const float* __restrict__ w2,
                                              const float* __restrict__ b2) {
    __shared__ float sm[2080];
    int bi = blockIdx.x;
    int t = threadIdx.x;

    if (bi < 512) {
        float(*tile)[65] = reinterpret_cast<float(*)[65]>(sm);
        int b = bi >> 7;
        int y = (bi >> 1) & 63;
        int ch = (bi & 1) * 32;
        int xi = t & 63;
        int ci = t >> 6;
#pragma unroll
        for (int pass = 0; pass < 8; ++pass) {
            int cl = pass * 4 + ci;
            tile[cl][xi] = feat[((b * 64 + ch + cl) * 64 + y) * 64 + xi];
        }
        __syncthreads();
        int cl = t & 31;
        int xj = t >> 5;
#pragma unroll
        for (int pass = 0; pass < 8; ++pass) {
            int x = pass * 8 + xj;
            g_featP[((b * PH + y + 1) * PH + x + 1) * 64 + ch + cl] = tile[cl][x];
        }
    } else if (bi < 539) {
        float* hdd = sm;            // [4][256]
        float* part = sm + 1024;    // [4][4][64]
        {
            float a0 = w1[t];
            float a1 = w1[256 + t];
            float a2 = w1[512 + t];
            float bb = b1[t];
#pragma unroll
            for (int pat = 0; pat < 4; ++pat) {
                float ry = (pat >> 1) ? 0.5f : 0.0f;
                float rx = (pat & 1) ? 0.5f : 0.0f;
                float v = ry * a0 + rx * a1 + 0.5f * a2 + bb;
                hdd[pat * 256 + t] = v > 0.0f ? v : 0.0f;
            }
        }
        __syncthreads();
        int jt = t & 63;
        int hc = t >> 6;
        int j = (bi - 512) * 64 + jt;
        int hb = hc * 64;
        float a0 = 0.f, a1 = 0.f, a2 = 0.f, a3 = 0.f;
        const float* w2p = w2 + hb * NOUT + j;
#pragma unroll 8
        for (int hh = 0; hh < 64; ++hh) {
            float wv = w2p[hh * NOUT];
            a0 += hdd[0 * 256 + hb + hh] * wv;
            a1 += hdd[1 * 256 + hb + hh] * wv;
            a2 += hdd[2 * 256 + hb + hh] * wv;
            a3 += hdd[3 * 256 + hb + hh] * wv;
        }
        part[(hc * 4 + 0) * 64 + jt] = a0;
        part[(hc * 4 + 1) * 64 + jt] = a1;
        part[(hc * 4 + 2) * 64 + jt] = a2;
        part[(hc * 4 + 3) * 64 + jt] = a3;
        __syncthreads();
        if (hc == 0) {
            float bias = b2[j];
            int k = j / 3;
            int o = j - k * 3;
            int c = k / 9;
            int tap = k - c * 9;
            int cgi = c >> 2;          // cg16 layout
            int cci = c & 3;
            int base = ((cci * 9 + tap) * 16 + cgi) * 12 + o;
#pragma unroll
            for (int pat = 0; pat < 4; ++pat) {
                float s = part[(0 * 4 + pat) * 64 + jt] + part[(1 * 4 + pat) * 64 + jt] +
                          part[(2 * 4 + pat) * 64 + jt] + part[(3 * 4 + pat) * 64 + jt] + bias;
                g_pw[base + pat * 3] = s;
            }
        }
    } else {
        int hb = bi - 539;
        int b = hb >> 1;
        int halfsel = hb & 1;
        for (int idx = t; idx < 130 * 64; idx += 256) {
            int p = halfsel * 130 + (idx >> 6);
            int c = idx & 63;
            int y, x;
            if (p < 66) { y = 0; x = p; }
            else if (p < 132) { y = 65; x = p - 66; }
            else if (p < 196) { x = 0; y = p - 131; }
            else { x = 65; y = p - 195; }
            g_featP[((b * PH + y) * PH + x) * 64 + c] = 0.0f;
        }
    }
}

// ---------------------------------------------------------------------------
// Main conv kernel: 512 blocks x 128 threads (R7 geometry) with explicit
// software pipelining. Warp = 2 quads; lane: cg = lane&15 (4-ch group),
// sub = lane>>4. Thread: 4 ch x 9 taps x 4 px x 12 out = 864 FFMA2.
// ---------------------------------------------------------------------------
#define FRLOAD(buf, rowp)                                                     \
    {                                                                         \
        _Pragma("unroll")                                                     \
        for (int i = 0; i < 6; ++i) {                                         \
            float4 v = *reinterpret_cast<const float4*>((rowp) + i * 64);     \
            fr[buf][i][0] = v.x; fr[buf][i][1] = v.y;                         \
            fr[buf][i][2] = v.z; fr[buf][i][3] = v.w;                         \
        }                                                                     \
    }

#define WLOAD(dA, dB, dC, ky, kx, cc)                                         \
    {                                                                         \
        const ulonglong2* wp = reinterpret_cast<const ulonglong2*>(           \
            pwl + ((cc) * 9 + (ky) * 3 + (kx)) * 192);                        \
        dA = wp[0]; dB = wp[1]; dC = wp[2];                                   \
    }

#define BURST(buf, kx, cc)                                                    \
    {                                                                         \
        _Pragma("unroll")                                                     \
        for (int px = 0; px < 4; ++px) {                                      \
            float fv = fr[buf][(kx) + px][cc];                                \
            unsigned long long fv2 = pk2(fv, fv);                             \
            ffma2(acc[px][0], fv2, wA.x);                                     \
            ffma2(acc[px][1], fv2, wA.y);                                     \
            ffma2(acc[px][2], fv2, wB.x);                                     \
            ffma2(acc[px][3], fv2, wB.y);                                     \
            ffma2(acc[px][4], fv2, wC.x);                                     \
            ffma2(acc[px][5], fv2, wC.y);                                     \
        }                                                                     \
    }

// one pipelined iteration: prefetch next weight triple, then burst current
#define STEP(buf, kx, cc, nky, nkx, ncc)                                      \
    WLOAD(nA, nB, nC, nky, nkx, ncc);                                         \
    BURST(buf, kx, cc);                                                       \
    wA = nA; wB = nB; wC = nC;

#define STEP_LAST(buf, kx, cc)                                                \
    BURST(buf, kx, cc);

__global__ __launch_bounds__(128, 4) void k_main(float* __restrict__ out) {
    __shared__ __align__(16) float pw_sm[576 * 12];
    int t = threadIdx.x;
    {
        const float4* g4 = reinterpret_cast<const float4*>(g_pw);
        float4* s4 = reinterpret_cast<float4*>(pw_sm);
#pragma unroll
        for (int i = 0; i < 14; ++i) {
            int idx = t + i * 128;
            if (idx < 1728) s4[idx] = g4[idx];
        }
    }
    __syncthreads();

    int lane = t & 31;
    int warp = t >> 5;
    int cg = lane & 15;
    int sub = lane >> 4;
    int quad = (blockIdx.x * 4 + warp) * 2 + sub;   // 0..4095
    int b = quad >> 10;
    int rem = quad & 1023;
    int y = rem >> 4;
    int x0 = (rem & 15) << 2;

    unsigned long long acc[4][6];
#pragma unroll
    for (int px = 0; px < 4; ++px)
#pragma unroll
        for (int p = 0; p < 6; ++p) acc[px][p] = 0ull;

    const float* pwl = pw_sm + cg * 12;   // 48B-aligned lane base
    const float* row0 = g_featP + ((b * PH + y) * PH + x0) * 64 + cg * 4;

    float fr[2][6][4];
    FRLOAD(0, row0);                       // ky=0 row

    ulonglong2 wA, wB, wC, nA, nB, nC;
    WLOAD(wA, wB, wC, 0, 0, 0);

    // ---- ky = 0 (buf 0); prefetch ky=1 row into buf 1 first ----
    FRLOAD(1, row0 + PH * 64);
    STEP(0, 0, 0, 0, 0, 1)  STEP(0, 0, 1, 0, 0, 2)  STEP(0, 0, 2, 0, 0, 3)
    STEP(0, 0, 3, 0, 1, 0)  STEP(0, 1, 0, 0, 1, 1)  STEP(0, 1, 1, 0, 1, 2)
    STEP(0, 1, 2, 0, 1, 3)  STEP(0, 1, 3, 0, 2, 0)  STEP(0, 2, 0, 0, 2, 1)
    STEP(0, 2, 1, 0, 2, 2)  STEP(0, 2, 2, 0, 2, 3)  STEP(0, 2, 3, 1, 0, 0)

    // ---- ky = 1 (buf 1); prefetch ky=2 row into buf 0 first ----
    FRLOAD(0, row0 + 2 * PH * 64);
    STEP(1, 0, 0, 1, 0, 1)  STEP(1, 0, 1, 1, 0, 2)  STEP(1, 0, 2, 1, 0, 3)
    STEP(1, 0, 3, 1, 1, 0)  STEP(1, 1, 0, 1, 1, 1)  STEP(1, 1, 1, 1, 1, 2)
    STEP(1, 1, 2, 1, 1, 3)  STEP(1, 1, 3, 1, 2, 0)  STEP(1, 2, 0, 1, 2, 1)
    STEP(1, 2, 1, 1, 2, 2)  STEP(1, 2, 2, 1, 2, 3)  STEP(1, 2, 3, 2, 0, 0)

    // ---- ky = 2 (buf 0) ----
    STEP(0, 0, 0, 2, 0, 1)  STEP(0, 0, 1, 2, 0, 2)  STEP(0, 0, 2, 2, 0, 3)
    STEP(0, 0, 3, 2, 1, 0)  STEP(0, 1, 0, 2, 1, 1)  STEP(0, 1, 1, 2, 1, 2)
    STEP(0, 1, 2, 2, 1, 3)  STEP(0, 1, 3, 2, 2, 0)  STEP(0, 2, 0, 2, 2, 1)
    STEP(0, 2, 1, 2, 2, 2)  STEP(0, 2, 2, 2, 2, 3)  STEP_LAST(0, 2, 3)

    // Unpack to 48 scalars: v[j], j = px*12 + pat*3 + o
    float v[48];
#pragma unroll
    for (int px = 0; px < 4; ++px)
#pragma unroll
        for (int p = 0; p < 6; ++p) {
            float a, bb;
            upk2(acc[px][p], a, bb);
            v[px * 12 + 2 * p] = a;
            v[px * 12 + 2 * p + 1] = bb;
        }

    // Reduce-scatter across the 16 cg lanes: lane ends owning 3 consecutive
    // j at base = 24*b0 + 12*b1 + 6*b2 + 3*b3 (bits of cg).
#pragma unroll
    for (int m = 1, n = 48; m < 16; m <<= 1, n >>= 1) {
        int half = n >> 1;
        bool hi = (cg & m) != 0;
#pragma unroll
        for (int i = 0; i < 48; ++i) {
            if (i >= half) break;
            float send = hi ? v[i] : v[i + half];
            float r = __shfl_xor_sync(0xffffffffu, send, m);
            v[i] = (hi ? v[i + half] : v[i]) + r;
        }
    }

    int base = 24 * (cg & 1) + 12 * ((cg >> 1) & 1) + 6 * ((cg >> 2) & 1) + 3 * ((cg >> 3) & 1);
    int px = base / 12;
    int r12 = base - px * 12;
    int dy = r12 / 6;
    int r6 = r12 - dy * 6;
    int dx = r6 / 3;

    int hrq = (2 * y + dy) * 128 + 2 * (x0 + px) + dx;
    float* op = out + (b * NQ + hrq) * 3;
    op[0] = v[0];
    op[1] = v[1];
    op[2] = v[2];
}

// ---------------------------------------------------------------------------
// Inputs (metadata order): feat, coord, cell, w1, b1, w2, b2.
// coord/cell are fully determined grids (collapsed analytically).
// ---------------------------------------------------------------------------
extern "C" void kernel_launch(void* const* d_in, const int* in_sizes, int n_in,
                              void* d_out, int out_size) {
    const float* feat = (const float*)d_in[0];
    const float* w1   = (const float*)d_in[3];
    const float* b1   = (const float*)d_in[4];
    const float* w2   = (const float*)d_in[5];
    const float* b2   = (const float*)d_in[6];
    float* out = (float*)d_out;

    k_prep<<<547, 256>>>(feat, w1, b1, w2, b2);
    k_main<<<512, 128>>>(out);
}